// round 13
// baseline (speedup 1.0000x reference)
#include <cuda_runtime.h>
#include <cuda_fp16.h>
#include <cstdint>

// ---------------------------------------------------------------------------
// B=512,N=200,C=512,NH=8,WS=5,HD=64.  M=102400 tokens.
// R13: kernels EXACTLY as validated R12 (best 727.1us). New: 4-way M-split +
// fork/join stream overlap so attention (ALU-bound) hides under GEMM1
// (tensor-bound) and GEMM2 quarters start as soon as their inputs are ready.
// ---------------------------------------------------------------------------
#define M_TOK   102400
#define K_DIM   512
#define N_QKV   1536
#define N_PROJ  512
#define WIN     5
#define HSCALE  0.125f
#define NKC     16        // K chunks of 32
#define CH_A    8192      // 128x32 fp16 A-image chunk bytes
#define CH_B    8192      // 32x128 fp16 B-image chunk bytes (paired frags)
#define STAGE_B 16384     // A(8K)+B(8K)
#define NSTAGE  3
#define NSPLIT  4
#define MT_Q    200       // m-tiles per quarter (800/4)
#define TOK_Q   25600     // tokens per quarter

// ---------------- scratch (device globals; no allocation) ------------------
__device__ __half  g_qkv[(size_t)M_TOK * N_QKV];
__device__ __half  gA_i[(size_t)M_TOK * K_DIM];
__device__ __half  gO_i[(size_t)M_TOK * K_DIM];
__device__ __half  gB1_i[(size_t)K_DIM * N_QKV];
__device__ __half  gB2_i[(size_t)K_DIM * N_PROJ];

// ---------------------------- helpers ---------------------------------------
__device__ __forceinline__ uint32_t smem_u32(const void* p) {
    uint32_t a;
    asm("{ .reg .u64 t; cvta.to.shared.u64 t, %1; cvt.u32.u64 %0, t; }"
        : "=r"(a) : "l"(p));
    return a;
}
__device__ __forceinline__ void cp16(uint32_t d, const void* s) {
    asm volatile("cp.async.cg.shared.global [%0], [%1], 16;"
                 :: "r"(d), "l"(s) : "memory");
}
__device__ __forceinline__ void cp_commit() {
    asm volatile("cp.async.commit_group;" ::: "memory");
}
__device__ __forceinline__ void cp_wait1() {
    asm volatile("cp.async.wait_group 1;" ::: "memory");
}
__device__ __forceinline__ void mma_f16(float4& d, uint4 a, uint32_t b0,
                                        uint32_t b1) {
    asm volatile(
        "mma.sync.aligned.m16n8k16.row.col.f32.f16.f16.f32 "
        "{%0,%1,%2,%3},{%4,%5,%6,%7},{%8,%9},{%0,%1,%2,%3};"
        : "+f"(d.x), "+f"(d.y), "+f"(d.z), "+f"(d.w)
        : "r"(a.x), "r"(a.y), "r"(a.z), "r"(a.w), "r"(b0), "r"(b1));
}
__device__ __forceinline__ unsigned short h_bits(__half h) {
    return *reinterpret_cast<unsigned short*>(&h);
}
__device__ __forceinline__ unsigned short h_single(float f) {
    __half hh = __float2half(f);
    return h_bits(hh);
}

// A-image inner offset (validated R3-R12):
__device__ __forceinline__ int a_inner(int row, int kin) {
    int kf = kin >> 4, mf = row >> 4, r = row & 15, c = kin & 15;
    return (kf * 8 + mf) * 512 + ((r & 7) * 4 + ((c & 7) >> 1)) * 16 +
           ((r >> 3) + ((c >> 3) << 1)) * 4 + (c & 1) * 2;
}
// Paired B-image inner offset (validated R6-R12):
__device__ __forceinline__ int bp_inner(int kr, int n) {
    int kf = kr >> 4, nfp = n >> 4, odd = (n >> 3) & 1;
    int t = (n & 7) * 4 + ((kr & 7) >> 1);
    return (kf * 8 + nfp) * 512 + t * 16 + odd * 8 + ((kr >> 3) & 1) * 4 +
           (kr & 1) * 2;
}

// ---------------------------------------------------------------------------
// conv A: x [M,512] fp32 -> single fp16 A images, smem-staged (R7/R12).
// ---------------------------------------------------------------------------
__global__ void __launch_bounds__(256)
conv_A_staged(const float* __restrict__ x, char* __restrict__ ai) {
    __shared__ char sh[CH_A];
    const int mt = blockIdx.x >> 4, kc = blockIdx.x & 15;
    const int t = threadIdx.x;
    const float* src = x + (size_t)mt * 128 * K_DIM + kc * 32;
#pragma unroll
    for (int i = 0; i < 4; ++i) {
        int f = t + i * 256;
        int row = f >> 3, c4 = (f & 7) * 4;
        float4 v = *(const float4*)(src + (size_t)row * K_DIM + c4);
        float vv[4] = {v.x, v.y, v.z, v.w};
#pragma unroll
        for (int jj = 0; jj < 4; ++jj)
            *(unsigned short*)(sh + a_inner(row, c4 + jj)) = h_single(vv[jj]);
    }
    __syncthreads();
    size_t ob = ((size_t)mt * NKC + kc) * CH_A;
    const uint4* shv = (const uint4*)sh;
    uint4* gh = (uint4*)(ai + ob);
    gh[t * 2] = shv[t * 2];
    gh[t * 2 + 1] = shv[t * 2 + 1];
}

// ---------------------------------------------------------------------------
// conv W: W [K,N] fp32 -> single fp16 paired B images, staged (R7/R12).
// ---------------------------------------------------------------------------
__global__ void __launch_bounds__(256)
conv_W_staged(const float* __restrict__ w, char* __restrict__ bi, int N) {
    __shared__ char sb[CH_B];
    const int nt = blockIdx.x >> 4, kc = blockIdx.x & 15;
    const int t = threadIdx.x;
    const float* src = w + (size_t)(kc * 32) * N + nt * 128;
#pragma unroll
    for (int i = 0; i < 4; ++i) {
        int f = t + i * 256;
        int kr = f >> 5, nc4 = (f & 31) * 4;
        float4 v = *(const float4*)(src + (size_t)kr * N + nc4);
        float vv[4] = {v.x, v.y, v.z, v.w};
#pragma unroll
        for (int jj = 0; jj < 4; ++jj)
            *(unsigned short*)(sb + bp_inner(kr, nc4 + jj)) = h_single(vv[jj]);
    }
    __syncthreads();
    size_t ob = ((size_t)nt * NKC + kc) * CH_B;
    const uint4* sv = (const uint4*)sb;
    uint4* gv = (uint4*)(bi + ob);
    gv[t * 2] = sv[t * 2];
    gv[t * 2 + 1] = sv[t * 2 + 1];
}

// ---------------------------------------------------------------------------
// 1-term fp16 HMMA GEMM (EXACT R7/R12 config — best measured).
// ---------------------------------------------------------------------------
template <bool HALF_OUT>
__global__ void __launch_bounds__(256, 2)
gemm_hmma_1t(const char* __restrict__ gAi, const char* __restrict__ gBi,
             const float* __restrict__ bias, void* __restrict__ Cv, int N) {
    extern __shared__ __align__(128) char smem[];
    const int tid = threadIdx.x;
    const int lane = tid & 31, wid = tid >> 5;
    const int wm = wid & 3, wn = wid >> 2;
    const uint32_t dynB = smem_u32(smem);

    const size_t aBase = (size_t)blockIdx.y * NKC * CH_A;
    const size_t bBase = (size_t)blockIdx.x * NKC * CH_B;

    float4 acc[2][8];
#pragma unroll
    for (int mi = 0; mi < 2; ++mi)
#pragma unroll
        for (int ni = 0; ni < 8; ++ni)
            acc[mi][ni] = make_float4(0.f, 0.f, 0.f, 0.f);

    auto issue = [&](int kc, int s) {
        uint32_t dst = dynB + s * STAGE_B;
        const char* ai = gAi + aBase + (size_t)kc * CH_A;
        const char* bi = gBi + bBase + (size_t)kc * CH_B;
        int off = tid * 16;
        cp16(dst + off, ai + off);
        cp16(dst + 4096 + off, ai + 4096 + off);
        cp16(dst + 8192 + off, bi + off);
        cp16(dst + 12288 + off, bi + 4096 + off);
    };

    issue(0, 0);
    cp_commit();
    issue(1, 1);
    cp_commit();

    for (int kc = 0; kc < NKC; ++kc) {
        const int s = kc % NSTAGE;
        cp_wait1();
        __syncthreads();
        if (kc + 2 < NKC) issue(kc + 2, (kc + 2) % NSTAGE);
        cp_commit();

        const char* st = smem + s * STAGE_B;
#pragma unroll
        for (int kf = 0; kf < 2; ++kf) {
            const char* af = st + (kf * 8 + wm * 2) * 512 + lane * 16;
            uint4 a0 = *(const uint4*)af;
            uint4 a1 = *(const uint4*)(af + 512);
            const char* bf =
                st + 8192 + (kf * 8 + wn * 4) * 512 + lane * 16;
#pragma unroll
            for (int p = 0; p < 4; ++p) {
                uint4 b = *(const uint4*)(bf + p * 512);
                int n0 = 2 * p, n1 = 2 * p + 1;
                mma_f16(acc[0][n0], a0, b.x, b.y);
                mma_f16(acc[1][n0], a1, b.x, b.y);
                mma_f16(acc[0][n1], a0, b.z, b.w);
                mma_f16(acc[1][n1], a1, b.z, b.w);
            }
        }
    }

    const int row0 = blockIdx.y * 128 + wm * 32 + (lane >> 2);
    const int col0 = blockIdx.x * 128 + wn * 64 + (lane & 3) * 2;
#pragma unroll
    for (int ni = 0; ni < 8; ++ni) {
        int c = col0 + ni * 8;
        float bx = bias[c], by = bias[c + 1];
#pragma unroll
        for (int mi = 0; mi < 2; ++mi) {
            float4 v = acc[mi][ni];
            if (HALF_OUT) {
                __half* C = (__half*)Cv;
                *(__half2*)(C + (size_t)(row0 + mi * 16) * N + c) =
                    __floats2half2_rn(v.x + bx, v.y + by);
                *(__half2*)(C + (size_t)(row0 + mi * 16 + 8) * N + c) =
                    __floats2half2_rn(v.z + bx, v.w + by);
            } else {
                float* C = (float*)Cv;
                *(float2*)(C + (size_t)(row0 + mi * 16) * N + c) =
                    make_float2(v.x + bx, v.y + by);
                *(float2*)(C + (size_t)(row0 + mi * 16 + 8) * N + c) =
                    make_float2(v.z + bx, v.w + by);
            }
        }
    }
}

// ---------------------------------------------------------------------------
// Windowed attention (EXACT R12, half2 lanes). Pointer-offset friendly:
// all indexing is relative to the passed base pointers.
// ---------------------------------------------------------------------------
__global__ void __launch_bounds__(256)
win_attn_kernel(const __half* __restrict__ qkv, char* __restrict__ oi) {
    const int win = blockIdx.x;
    const int h = threadIdx.x >> 5;
    const int lane = threadIdx.x & 31;
    const int m0 = win * WIN;

    const __half2* base =
        (const __half2*)(qkv + (size_t)m0 * N_QKV + h * 64);

    float2 q[WIN], k[WIN], v[WIN];
#pragma unroll
    for (int i = 0; i < WIN; ++i) {
        const __half2* r = base + (size_t)i * (N_QKV / 2);
        q[i] = __half22float2(r[lane]);
        k[i] = __half22float2(r[256 + lane]);
        v[i] = __half22float2(r[512 + lane]);
    }

    float s[WIN][WIN];
#pragma unroll
    for (int i = 0; i < WIN; ++i)
#pragma unroll
        for (int j = 0; j < WIN; ++j) {
            float p = q[i].x * k[j].x + q[i].y * k[j].y;
            p += __shfl_xor_sync(0xffffffffu, p, 16);
            p += __shfl_xor_sync(0xffffffffu, p, 8);
            p += __shfl_xor_sync(0xffffffffu, p, 4);
            p += __shfl_xor_sync(0xffffffffu, p, 2);
            p += __shfl_xor_sync(0xffffffffu, p, 1);
            s[i][j] = p * HSCALE;
        }

    const int chunk = 2 * h + (lane >> 4);
    const int kin = (lane & 15) * 2;

#pragma unroll
    for (int i = 0; i < WIN; ++i) {
        float mx = s[i][0];
#pragma unroll
        for (int j = 1; j < WIN; ++j) mx = fmaxf(mx, s[i][j]);
        float sum = 0.0f;
#pragma unroll
        for (int j = 0; j < WIN; ++j) {
            s[i][j] = __expf(s[i][j] - mx);
            sum += s[i][j];
        }
        float inv = 1.0f / sum;
        float o0 = 0.0f, o1 = 0.0f;
#pragma unroll
        for (int j = 0; j < WIN; ++j) {
            float a = s[i][j] * inv;
            o0 += a * v[j].x;
            o1 += a * v[j].y;
        }
        int m = m0 + i;
        size_t tb = ((size_t)(m >> 7) * NKC + chunk) * CH_A +
                    a_inner(m & 127, kin);
        __half2 hv = __floats2half2_rn(o0, o1);
        *(uint32_t*)(oi + tb) = *reinterpret_cast<uint32_t*>(&hv);
    }
}

// ---------------------------------------------------------------------------
// kernel_launch: 4-way M-split + fork/join overlap.
//   stream0 (capture): convs, G1(q) x4, G2(q) x4
//   side stream     : attn(q) after G1(q); G2(q) waits attn(q).
// All quarters are pure pointer offsets (TOK_Q = 200 m-tiles exactly).
// ---------------------------------------------------------------------------
extern "C" void kernel_launch(void* const* d_in, const int* in_sizes, int n_in,
                              void* d_out, int out_size) {
    const float* x      = (const float*)d_in[0];
    const float* qkv_w  = (const float*)d_in[1];
    const float* qkv_b  = (const float*)d_in[2];
    const float* proj_w = (const float*)d_in[3];
    const float* proj_b = (const float*)d_in[4];
    float* out = (float*)d_out;

    __half* qkvp;
    char *Ai, *Oi, *B1, *B2;
    cudaGetSymbolAddress((void**)&qkvp, g_qkv);
    cudaGetSymbolAddress((void**)&Ai, gA_i);
    cudaGetSymbolAddress((void**)&Oi, gO_i);
    cudaGetSymbolAddress((void**)&B1, gB1_i);
    cudaGetSymbolAddress((void**)&B2, gB2_i);

    static bool init_done = false;
    static cudaStream_t s1;
    static cudaEvent_t evG1[NSPLIT], evAt[NSPLIT];
    if (!init_done) {
        cudaFuncSetAttribute(gemm_hmma_1t<true>,
                             cudaFuncAttributeMaxDynamicSharedMemorySize,
                             NSTAGE * STAGE_B);
        cudaFuncSetAttribute(gemm_hmma_1t<false>,
                             cudaFuncAttributeMaxDynamicSharedMemorySize,
                             NSTAGE * STAGE_B);
        cudaStreamCreateWithFlags(&s1, cudaStreamNonBlocking);
        for (int q = 0; q < NSPLIT; ++q) {
            cudaEventCreateWithFlags(&evG1[q], cudaEventDisableTiming);
            cudaEventCreateWithFlags(&evAt[q], cudaEventDisableTiming);
        }
        init_done = true;
    }

    // convs (stream 0)
    conv_A_staged<<<(M_TOK / 128) * NKC, 256>>>(x, Ai);
    conv_W_staged<<<(N_QKV / 128) * NKC, 256>>>(qkv_w, B1, N_QKV);
    conv_W_staged<<<(N_PROJ / 128) * NKC, 256>>>(proj_w, B2, N_PROJ);

    // GEMM1 quarters on stream 0, each followed by an event
    for (int q = 0; q < NSPLIT; ++q) {
        const char* Aq = Ai + (size_t)q * MT_Q * NKC * CH_A;
        __half* Cq = qkvp + (size_t)q * TOK_Q * N_QKV;
        dim3 grid(N_QKV / 128, MT_Q);
        gemm_hmma_1t<true><<<grid, 256, NSTAGE * STAGE_B>>>(Aq, B1, qkv_b,
                                                            Cq, N_QKV);
        cudaEventRecord(evG1[q], 0);
    }

    // attention quarters on side stream, gated on their GEMM1 quarter
    for (int q = 0; q < NSPLIT; ++q) {
        cudaStreamWaitEvent(s1, evG1[q], 0);
        const __half* qkvq = qkvp + (size_t)q * TOK_Q * N_QKV;
        char* Oq = Oi + (size_t)q * MT_Q * NKC * CH_A;
        win_attn_kernel<<<TOK_Q / WIN, 256, 0, s1>>>(qkvq, Oq);
        cudaEventRecord(evAt[q], s1);
    }

    // GEMM2 quarters on stream 0, each gated on its attention quarter
    for (int q = 0; q < NSPLIT; ++q) {
        cudaStreamWaitEvent(0, evAt[q], 0);
        const char* Oq = Oi + (size_t)q * MT_Q * NKC * CH_A;
        float* outq = out + (size_t)q * TOK_Q * N_PROJ;
        dim3 grid(N_PROJ / 128, MT_Q);
        gemm_hmma_1t<false><<<grid, 256, NSTAGE * STAGE_B>>>(Oq, B2, proj_b,
                                                             outq, N_PROJ);
    }
}

// round 15
// speedup vs baseline: 1.0163x; 1.0163x over previous
#include <cuda_runtime.h>
#include <cuda_fp16.h>
#include <cstdint>

// ---------------------------------------------------------------------------
// B=512,N=200,C=512,NH=8,WS=5,HD=64.  M=102400 tokens.
// R15: all kernels EXACTLY as validated R12 (best 727.1us). conv_W(B1/B2) on
// a side stream concurrent with conv_A — with a LEGAL capture fork this time:
// s1 first waits an event recorded on the capture stream, then launches.
// ---------------------------------------------------------------------------
#define M_TOK   102400
#define K_DIM   512
#define N_QKV   1536
#define N_PROJ  512
#define WIN     5
#define HSCALE  0.125f
#define NKC     16        // K chunks of 32
#define CH_A    8192      // 128x32 fp16 A-image chunk bytes
#define CH_B    8192      // 32x128 fp16 B-image chunk bytes (paired frags)
#define STAGE_B 16384     // A(8K)+B(8K)
#define NSTAGE  3

// ---------------- scratch (device globals; no allocation) ------------------
__device__ __half  g_qkv[(size_t)M_TOK * N_QKV];
__device__ __half  gA_i[(size_t)M_TOK * K_DIM];
__device__ __half  gO_i[(size_t)M_TOK * K_DIM];
__device__ __half  gB1_i[(size_t)K_DIM * N_QKV];
__device__ __half  gB2_i[(size_t)K_DIM * N_PROJ];

// ---------------------------- helpers ---------------------------------------
__device__ __forceinline__ uint32_t smem_u32(const void* p) {
    uint32_t a;
    asm("{ .reg .u64 t; cvta.to.shared.u64 t, %1; cvt.u32.u64 %0, t; }"
        : "=r"(a) : "l"(p));
    return a;
}
__device__ __forceinline__ void cp16(uint32_t d, const void* s) {
    asm volatile("cp.async.cg.shared.global [%0], [%1], 16;"
                 :: "r"(d), "l"(s) : "memory");
}
__device__ __forceinline__ void cp_commit() {
    asm volatile("cp.async.commit_group;" ::: "memory");
}
__device__ __forceinline__ void cp_wait1() {
    asm volatile("cp.async.wait_group 1;" ::: "memory");
}
__device__ __forceinline__ void mma_f16(float4& d, uint4 a, uint32_t b0,
                                        uint32_t b1) {
    asm volatile(
        "mma.sync.aligned.m16n8k16.row.col.f32.f16.f16.f32 "
        "{%0,%1,%2,%3},{%4,%5,%6,%7},{%8,%9},{%0,%1,%2,%3};"
        : "+f"(d.x), "+f"(d.y), "+f"(d.z), "+f"(d.w)
        : "r"(a.x), "r"(a.y), "r"(a.z), "r"(a.w), "r"(b0), "r"(b1));
}
__device__ __forceinline__ unsigned short h_bits(__half h) {
    return *reinterpret_cast<unsigned short*>(&h);
}
__device__ __forceinline__ unsigned short h_single(float f) {
    __half hh = __float2half(f);
    return h_bits(hh);
}

// A-image inner offset (validated R3-R13):
__device__ __forceinline__ int a_inner(int row, int kin) {
    int kf = kin >> 4, mf = row >> 4, r = row & 15, c = kin & 15;
    return (kf * 8 + mf) * 512 + ((r & 7) * 4 + ((c & 7) >> 1)) * 16 +
           ((r >> 3) + ((c >> 3) << 1)) * 4 + (c & 1) * 2;
}
// Paired B-image inner offset (validated R6-R13):
__device__ __forceinline__ int bp_inner(int kr, int n) {
    int kf = kr >> 4, nfp = n >> 4, odd = (n >> 3) & 1;
    int t = (n & 7) * 4 + ((kr & 7) >> 1);
    return (kf * 8 + nfp) * 512 + t * 16 + odd * 8 + ((kr >> 3) & 1) * 4 +
           (kr & 1) * 2;
}

// ---------------------------------------------------------------------------
// conv A: x [M,512] fp32 -> single fp16 A images, smem-staged (R7/R12).
// ---------------------------------------------------------------------------
__global__ void __launch_bounds__(256)
conv_A_staged(const float* __restrict__ x, char* __restrict__ ai) {
    __shared__ char sh[CH_A];
    const int mt = blockIdx.x >> 4, kc = blockIdx.x & 15;
    const int t = threadIdx.x;
    const float* src = x + (size_t)mt * 128 * K_DIM + kc * 32;
#pragma unroll
    for (int i = 0; i < 4; ++i) {
        int f = t + i * 256;
        int row = f >> 3, c4 = (f & 7) * 4;
        float4 v = *(const float4*)(src + (size_t)row * K_DIM + c4);
        float vv[4] = {v.x, v.y, v.z, v.w};
#pragma unroll
        for (int jj = 0; jj < 4; ++jj)
            *(unsigned short*)(sh + a_inner(row, c4 + jj)) = h_single(vv[jj]);
    }
    __syncthreads();
    size_t ob = ((size_t)mt * NKC + kc) * CH_A;
    const uint4* shv = (const uint4*)sh;
    uint4* gh = (uint4*)(ai + ob);
    gh[t * 2] = shv[t * 2];
    gh[t * 2 + 1] = shv[t * 2 + 1];
}

// ---------------------------------------------------------------------------
// conv W: W [K,N] fp32 -> single fp16 paired B images, staged (R7/R12).
// ---------------------------------------------------------------------------
__global__ void __launch_bounds__(256)
conv_W_staged(const float* __restrict__ w, char* __restrict__ bi, int N) {
    __shared__ char sb[CH_B];
    const int nt = blockIdx.x >> 4, kc = blockIdx.x & 15;
    const int t = threadIdx.x;
    const float* src = w + (size_t)(kc * 32) * N + nt * 128;
#pragma unroll
    for (int i = 0; i < 4; ++i) {
        int f = t + i * 256;
        int kr = f >> 5, nc4 = (f & 31) * 4;
        float4 v = *(const float4*)(src + (size_t)kr * N + nc4);
        float vv[4] = {v.x, v.y, v.z, v.w};
#pragma unroll
        for (int jj = 0; jj < 4; ++jj)
            *(unsigned short*)(sb + bp_inner(kr, nc4 + jj)) = h_single(vv[jj]);
    }
    __syncthreads();
    size_t ob = ((size_t)nt * NKC + kc) * CH_B;
    const uint4* sv = (const uint4*)sb;
    uint4* gv = (uint4*)(bi + ob);
    gv[t * 2] = sv[t * 2];
    gv[t * 2 + 1] = sv[t * 2 + 1];
}

// ---------------------------------------------------------------------------
// 1-term fp16 HMMA GEMM (EXACT R7/R12 config — best measured).
// ---------------------------------------------------------------------------
template <bool HALF_OUT>
__global__ void __launch_bounds__(256, 2)
gemm_hmma_1t(const char* __restrict__ gAi, const char* __restrict__ gBi,
             const float* __restrict__ bias, void* __restrict__ Cv, int N) {
    extern __shared__ __align__(128) char smem[];
    const int tid = threadIdx.x;
    const int lane = tid & 31, wid = tid >> 5;
    const int wm = wid & 3, wn = wid >> 2;
    const uint32_t dynB = smem_u32(smem);

    const size_t aBase = (size_t)blockIdx.y * NKC * CH_A;
    const size_t bBase = (size_t)blockIdx.x * NKC * CH_B;

    float4 acc[2][8];
#pragma unroll
    for (int mi = 0; mi < 2; ++mi)
#pragma unroll
        for (int ni = 0; ni < 8; ++ni)
            acc[mi][ni] = make_float4(0.f, 0.f, 0.f, 0.f);

    auto issue = [&](int kc, int s) {
        uint32_t dst = dynB + s * STAGE_B;
        const char* ai = gAi + aBase + (size_t)kc * CH_A;
        const char* bi = gBi + bBase + (size_t)kc * CH_B;
        int off = tid * 16;
        cp16(dst + off, ai + off);
        cp16(dst + 4096 + off, ai + 4096 + off);
        cp16(dst + 8192 + off, bi + off);
        cp16(dst + 12288 + off, bi + 4096 + off);
    };

    issue(0, 0);
    cp_commit();
    issue(1, 1);
    cp_commit();

    for (int kc = 0; kc < NKC; ++kc) {
        const int s = kc % NSTAGE;
        cp_wait1();
        __syncthreads();
        if (kc + 2 < NKC) issue(kc + 2, (kc + 2) % NSTAGE);
        cp_commit();

        const char* st = smem + s * STAGE_B;
#pragma unroll
        for (int kf = 0; kf < 2; ++kf) {
            const char* af = st + (kf * 8 + wm * 2) * 512 + lane * 16;
            uint4 a0 = *(const uint4*)af;
            uint4 a1 = *(const uint4*)(af + 512);
            const char* bf =
                st + 8192 + (kf * 8 + wn * 4) * 512 + lane * 16;
#pragma unroll
            for (int p = 0; p < 4; ++p) {
                uint4 b = *(const uint4*)(bf + p * 512);
                int n0 = 2 * p, n1 = 2 * p + 1;
                mma_f16(acc[0][n0], a0, b.x, b.y);
                mma_f16(acc[1][n0], a1, b.x, b.y);
                mma_f16(acc[0][n1], a0, b.z, b.w);
                mma_f16(acc[1][n1], a1, b.z, b.w);
            }
        }
    }

    const int row0 = blockIdx.y * 128 + wm * 32 + (lane >> 2);
    const int col0 = blockIdx.x * 128 + wn * 64 + (lane & 3) * 2;
#pragma unroll
    for (int ni = 0; ni < 8; ++ni) {
        int c = col0 + ni * 8;
        float bx = bias[c], by = bias[c + 1];
#pragma unroll
        for (int mi = 0; mi < 2; ++mi) {
            float4 v = acc[mi][ni];
            if (HALF_OUT) {
                __half* C = (__half*)Cv;
                *(__half2*)(C + (size_t)(row0 + mi * 16) * N + c) =
                    __floats2half2_rn(v.x + bx, v.y + by);
                *(__half2*)(C + (size_t)(row0 + mi * 16 + 8) * N + c) =
                    __floats2half2_rn(v.z + bx, v.w + by);
            } else {
                float* C = (float*)Cv;
                *(float2*)(C + (size_t)(row0 + mi * 16) * N + c) =
                    make_float2(v.x + bx, v.y + by);
                *(float2*)(C + (size_t)(row0 + mi * 16 + 8) * N + c) =
                    make_float2(v.z + bx, v.w + by);
            }
        }
    }
}

// ---------------------------------------------------------------------------
// Windowed attention (EXACT R12, half2 lanes).
// ---------------------------------------------------------------------------
__global__ void __launch_bounds__(256)
win_attn_kernel(const __half* __restrict__ qkv, char* __restrict__ oi) {
    const int win = blockIdx.x;
    const int h = threadIdx.x >> 5;
    const int lane = threadIdx.x & 31;
    const int m0 = win * WIN;

    const __half2* base =
        (const __half2*)(qkv + (size_t)m0 * N_QKV + h * 64);

    float2 q[WIN], k[WIN], v[WIN];
#pragma unroll
    for (int i = 0; i < WIN; ++i) {
        const __half2* r = base + (size_t)i * (N_QKV / 2);
        q[i] = __half22float2(r[lane]);
        k[i] = __half22float2(r[256 + lane]);
        v[i] = __half22float2(r[512 + lane]);
    }

    float s[WIN][WIN];
#pragma unroll
    for (int i = 0; i < WIN; ++i)
#pragma unroll
        for (int j = 0; j < WIN; ++j) {
            float p = q[i].x * k[j].x + q[i].y * k[j].y;
            p += __shfl_xor_sync(0xffffffffu, p, 16);
            p += __shfl_xor_sync(0xffffffffu, p, 8);
            p += __shfl_xor_sync(0xffffffffu, p, 4);
            p += __shfl_xor_sync(0xffffffffu, p, 2);
            p += __shfl_xor_sync(0xffffffffu, p, 1);
            s[i][j] = p * HSCALE;
        }

    const int chunk = 2 * h + (lane >> 4);
    const int kin = (lane & 15) * 2;

#pragma unroll
    for (int i = 0; i < WIN; ++i) {
        float mx = s[i][0];
#pragma unroll
        for (int j = 1; j < WIN; ++j) mx = fmaxf(mx, s[i][j]);
        float sum = 0.0f;
#pragma unroll
        for (int j = 0; j < WIN; ++j) {
            s[i][j] = __expf(s[i][j] - mx);
            sum += s[i][j];
        }
        float inv = 1.0f / sum;
        float o0 = 0.0f, o1 = 0.0f;
#pragma unroll
        for (int j = 0; j < WIN; ++j) {
            float a = s[i][j] * inv;
            o0 += a * v[j].x;
            o1 += a * v[j].y;
        }
        int m = m0 + i;
        size_t tb = ((size_t)(m >> 7) * NKC + chunk) * CH_A +
                    a_inner(m & 127, kin);
        __half2 hv = __floats2half2_rn(o0, o1);
        *(uint32_t*)(oi + tb) = *reinterpret_cast<uint32_t*>(&hv);
    }
}

// ---------------------------------------------------------------------------
// kernel_launch: legal capture fork — s1 waits an event recorded on the
// capture stream BEFORE any s1 work; conv_W's overlap conv_A; single join
// before GEMM1. GEMM1 / attn / GEMM2 monolithic (R12 structure).
// ---------------------------------------------------------------------------
extern "C" void kernel_launch(void* const* d_in, const int* in_sizes, int n_in,
                              void* d_out, int out_size) {
    const float* x      = (const float*)d_in[0];
    const float* qkv_w  = (const float*)d_in[1];
    const float* qkv_b  = (const float*)d_in[2];
    const float* proj_w = (const float*)d_in[3];
    const float* proj_b = (const float*)d_in[4];
    float* out = (float*)d_out;

    __half* qkvp;
    char *Ai, *Oi, *B1, *B2;
    cudaGetSymbolAddress((void**)&qkvp, g_qkv);
    cudaGetSymbolAddress((void**)&Ai, gA_i);
    cudaGetSymbolAddress((void**)&Oi, gO_i);
    cudaGetSymbolAddress((void**)&B1, gB1_i);
    cudaGetSymbolAddress((void**)&B2, gB2_i);

    static bool init_done = false;
    static cudaStream_t s1;
    static cudaEvent_t evFork, evW;
    if (!init_done) {
        cudaFuncSetAttribute(gemm_hmma_1t<true>,
                             cudaFuncAttributeMaxDynamicSharedMemorySize,
                             NSTAGE * STAGE_B);
        cudaFuncSetAttribute(gemm_hmma_1t<false>,
                             cudaFuncAttributeMaxDynamicSharedMemorySize,
                             NSTAGE * STAGE_B);
        cudaStreamCreateWithFlags(&s1, cudaStreamNonBlocking);
        cudaEventCreateWithFlags(&evFork, cudaEventDisableTiming);
        cudaEventCreateWithFlags(&evW, cudaEventDisableTiming);
        init_done = true;
    }

    // legal fork: event on capture stream, side stream waits it first
    cudaEventRecord(evFork, 0);
    cudaStreamWaitEvent(s1, evFork, 0);

    // conv_W's on side stream (concurrent with conv_A below)
    conv_W_staged<<<(N_QKV / 128) * NKC, 256, 0, s1>>>(qkv_w, B1, N_QKV);
    conv_W_staged<<<(N_PROJ / 128) * NKC, 256, 0, s1>>>(proj_w, B2, N_PROJ);
    cudaEventRecord(evW, s1);

    // conv_A on main stream
    conv_A_staged<<<(M_TOK / 128) * NKC, 256>>>(x, Ai);

    // join before GEMM1
    cudaStreamWaitEvent(0, evW, 0);

    {   // GEMM1 -> g_qkv (fp16)
        dim3 grid(N_QKV / 128, M_TOK / 128);
        gemm_hmma_1t<true><<<grid, 256, NSTAGE * STAGE_B>>>(Ai, B1, qkv_b,
                                                            qkvp, N_QKV);
    }

    win_attn_kernel<<<M_TOK / WIN, 256>>>(qkvp, Oi);

    {   // GEMM2 -> out (fp32)
        dim3 grid(N_PROJ / 128, M_TOK / 128);
        gemm_hmma_1t<false><<<grid, 256, NSTAGE * STAGE_B>>>(Oi, B2, proj_b,
                                                             out, N_PROJ);
    }
}

// round 16
// speedup vs baseline: 1.0873x; 1.0699x over previous
#include <cuda_runtime.h>
#include <cuda_fp16.h>
#include <cstdint>

// ---------------------------------------------------------------------------
// B=512,N=200,C=512,NH=8,WS=5,HD=64.  M=102400 tokens.
// R16: GEMMs/convs/stream-fork EXACTLY as R15 (best 725.3us). Attention
// restructured: 16 lanes per head (warp = 2 heads), 4-stage butterfly,
// uint2 loads -> 2.5x fewer SHFLs, half the load/MUFU instructions.
// ---------------------------------------------------------------------------
#define M_TOK   102400
#define K_DIM   512
#define N_QKV   1536
#define N_PROJ  512
#define WIN     5
#define HSCALE  0.125f
#define NKC     16        // K chunks of 32
#define CH_A    8192      // 128x32 fp16 A-image chunk bytes
#define CH_B    8192      // 32x128 fp16 B-image chunk bytes (paired frags)
#define STAGE_B 16384     // A(8K)+B(8K)
#define NSTAGE  3

// ---------------- scratch (device globals; no allocation) ------------------
__device__ __half  g_qkv[(size_t)M_TOK * N_QKV];
__device__ __half  gA_i[(size_t)M_TOK * K_DIM];
__device__ __half  gO_i[(size_t)M_TOK * K_DIM];
__device__ __half  gB1_i[(size_t)K_DIM * N_QKV];
__device__ __half  gB2_i[(size_t)K_DIM * N_PROJ];

// ---------------------------- helpers ---------------------------------------
__device__ __forceinline__ uint32_t smem_u32(const void* p) {
    uint32_t a;
    asm("{ .reg .u64 t; cvta.to.shared.u64 t, %1; cvt.u32.u64 %0, t; }"
        : "=r"(a) : "l"(p));
    return a;
}
__device__ __forceinline__ void cp16(uint32_t d, const void* s) {
    asm volatile("cp.async.cg.shared.global [%0], [%1], 16;"
                 :: "r"(d), "l"(s) : "memory");
}
__device__ __forceinline__ void cp_commit() {
    asm volatile("cp.async.commit_group;" ::: "memory");
}
__device__ __forceinline__ void cp_wait1() {
    asm volatile("cp.async.wait_group 1;" ::: "memory");
}
__device__ __forceinline__ void mma_f16(float4& d, uint4 a, uint32_t b0,
                                        uint32_t b1) {
    asm volatile(
        "mma.sync.aligned.m16n8k16.row.col.f32.f16.f16.f32 "
        "{%0,%1,%2,%3},{%4,%5,%6,%7},{%8,%9},{%0,%1,%2,%3};"
        : "+f"(d.x), "+f"(d.y), "+f"(d.z), "+f"(d.w)
        : "r"(a.x), "r"(a.y), "r"(a.z), "r"(a.w), "r"(b0), "r"(b1));
}
__device__ __forceinline__ unsigned short h_bits(__half h) {
    return *reinterpret_cast<unsigned short*>(&h);
}
__device__ __forceinline__ unsigned short h_single(float f) {
    __half hh = __float2half(f);
    return h_bits(hh);
}

// A-image inner offset (validated R3-R15):
__device__ __forceinline__ int a_inner(int row, int kin) {
    int kf = kin >> 4, mf = row >> 4, r = row & 15, c = kin & 15;
    return (kf * 8 + mf) * 512 + ((r & 7) * 4 + ((c & 7) >> 1)) * 16 +
           ((r >> 3) + ((c >> 3) << 1)) * 4 + (c & 1) * 2;
}
// Paired B-image inner offset (validated R6-R15):
__device__ __forceinline__ int bp_inner(int kr, int n) {
    int kf = kr >> 4, nfp = n >> 4, odd = (n >> 3) & 1;
    int t = (n & 7) * 4 + ((kr & 7) >> 1);
    return (kf * 8 + nfp) * 512 + t * 16 + odd * 8 + ((kr >> 3) & 1) * 4 +
           (kr & 1) * 2;
}

// ---------------------------------------------------------------------------
// conv A: x [M,512] fp32 -> single fp16 A images, smem-staged (R7/R12).
// ---------------------------------------------------------------------------
__global__ void __launch_bounds__(256)
conv_A_staged(const float* __restrict__ x, char* __restrict__ ai) {
    __shared__ char sh[CH_A];
    const int mt = blockIdx.x >> 4, kc = blockIdx.x & 15;
    const int t = threadIdx.x;
    const float* src = x + (size_t)mt * 128 * K_DIM + kc * 32;
#pragma unroll
    for (int i = 0; i < 4; ++i) {
        int f = t + i * 256;
        int row = f >> 3, c4 = (f & 7) * 4;
        float4 v = *(const float4*)(src + (size_t)row * K_DIM + c4);
        float vv[4] = {v.x, v.y, v.z, v.w};
#pragma unroll
        for (int jj = 0; jj < 4; ++jj)
            *(unsigned short*)(sh + a_inner(row, c4 + jj)) = h_single(vv[jj]);
    }
    __syncthreads();
    size_t ob = ((size_t)mt * NKC + kc) * CH_A;
    const uint4* shv = (const uint4*)sh;
    uint4* gh = (uint4*)(ai + ob);
    gh[t * 2] = shv[t * 2];
    gh[t * 2 + 1] = shv[t * 2 + 1];
}

// ---------------------------------------------------------------------------
// conv W: W [K,N] fp32 -> single fp16 paired B images, staged (R7/R12).
// ---------------------------------------------------------------------------
__global__ void __launch_bounds__(256)
conv_W_staged(const float* __restrict__ w, char* __restrict__ bi, int N) {
    __shared__ char sb[CH_B];
    const int nt = blockIdx.x >> 4, kc = blockIdx.x & 15;
    const int t = threadIdx.x;
    const float* src = w + (size_t)(kc * 32) * N + nt * 128;
#pragma unroll
    for (int i = 0; i < 4; ++i) {
        int f = t + i * 256;
        int kr = f >> 5, nc4 = (f & 31) * 4;
        float4 v = *(const float4*)(src + (size_t)kr * N + nc4);
        float vv[4] = {v.x, v.y, v.z, v.w};
#pragma unroll
        for (int jj = 0; jj < 4; ++jj)
            *(unsigned short*)(sb + bp_inner(kr, nc4 + jj)) = h_single(vv[jj]);
    }
    __syncthreads();
    size_t ob = ((size_t)nt * NKC + kc) * CH_B;
    const uint4* sv = (const uint4*)sb;
    uint4* gv = (uint4*)(bi + ob);
    gv[t * 2] = sv[t * 2];
    gv[t * 2 + 1] = sv[t * 2 + 1];
}

// ---------------------------------------------------------------------------
// 1-term fp16 HMMA GEMM (EXACT R7/R12 config — best measured).
// ---------------------------------------------------------------------------
template <bool HALF_OUT>
__global__ void __launch_bounds__(256, 2)
gemm_hmma_1t(const char* __restrict__ gAi, const char* __restrict__ gBi,
             const float* __restrict__ bias, void* __restrict__ Cv, int N) {
    extern __shared__ __align__(128) char smem[];
    const int tid = threadIdx.x;
    const int lane = tid & 31, wid = tid >> 5;
    const int wm = wid & 3, wn = wid >> 2;
    const uint32_t dynB = smem_u32(smem);

    const size_t aBase = (size_t)blockIdx.y * NKC * CH_A;
    const size_t bBase = (size_t)blockIdx.x * NKC * CH_B;

    float4 acc[2][8];
#pragma unroll
    for (int mi = 0; mi < 2; ++mi)
#pragma unroll
        for (int ni = 0; ni < 8; ++ni)
            acc[mi][ni] = make_float4(0.f, 0.f, 0.f, 0.f);

    auto issue = [&](int kc, int s) {
        uint32_t dst = dynB + s * STAGE_B;
        const char* ai = gAi + aBase + (size_t)kc * CH_A;
        const char* bi = gBi + bBase + (size_t)kc * CH_B;
        int off = tid * 16;
        cp16(dst + off, ai + off);
        cp16(dst + 4096 + off, ai + 4096 + off);
        cp16(dst + 8192 + off, bi + off);
        cp16(dst + 12288 + off, bi + 4096 + off);
    };

    issue(0, 0);
    cp_commit();
    issue(1, 1);
    cp_commit();

    for (int kc = 0; kc < NKC; ++kc) {
        const int s = kc % NSTAGE;
        cp_wait1();
        __syncthreads();
        if (kc + 2 < NKC) issue(kc + 2, (kc + 2) % NSTAGE);
        cp_commit();

        const char* st = smem + s * STAGE_B;
#pragma unroll
        for (int kf = 0; kf < 2; ++kf) {
            const char* af = st + (kf * 8 + wm * 2) * 512 + lane * 16;
            uint4 a0 = *(const uint4*)af;
            uint4 a1 = *(const uint4*)(af + 512);
            const char* bf =
                st + 8192 + (kf * 8 + wn * 4) * 512 + lane * 16;
#pragma unroll
            for (int p = 0; p < 4; ++p) {
                uint4 b = *(const uint4*)(bf + p * 512);
                int n0 = 2 * p, n1 = 2 * p + 1;
                mma_f16(acc[0][n0], a0, b.x, b.y);
                mma_f16(acc[1][n0], a1, b.x, b.y);
                mma_f16(acc[0][n1], a0, b.z, b.w);
                mma_f16(acc[1][n1], a1, b.z, b.w);
            }
        }
    }

    const int row0 = blockIdx.y * 128 + wm * 32 + (lane >> 2);
    const int col0 = blockIdx.x * 128 + wn * 64 + (lane & 3) * 2;
#pragma unroll
    for (int ni = 0; ni < 8; ++ni) {
        int c = col0 + ni * 8;
        float bx = bias[c], by = bias[c + 1];
#pragma unroll
        for (int mi = 0; mi < 2; ++mi) {
            float4 v = acc[mi][ni];
            if (HALF_OUT) {
                __half* C = (__half*)Cv;
                *(__half2*)(C + (size_t)(row0 + mi * 16) * N + c) =
                    __floats2half2_rn(v.x + bx, v.y + by);
                *(__half2*)(C + (size_t)(row0 + mi * 16 + 8) * N + c) =
                    __floats2half2_rn(v.z + bx, v.w + by);
            } else {
                float* C = (float*)Cv;
                *(float2*)(C + (size_t)(row0 + mi * 16) * N + c) =
                    make_float2(v.x + bx, v.y + by);
                *(float2*)(C + (size_t)(row0 + mi * 16 + 8) * N + c) =
                    make_float2(v.z + bx, v.w + by);
            }
        }
    }
}

// ---------------------------------------------------------------------------
// Windowed attention, 16 lanes per head: block = 128 thr = 4 warps;
// warp w serves heads 2w (lanes 0-15) and 2w+1 (lanes 16-31).
// Lane owns 4 dims (one uint2 load per row-section). 4-stage butterfly.
// ---------------------------------------------------------------------------
__global__ void __launch_bounds__(128)
win_attn_kernel(const __half* __restrict__ qkv, char* __restrict__ oi) {
    const int win = blockIdx.x;
    const int wid = threadIdx.x >> 5;
    const int lane = threadIdx.x & 31;
    const int hl = lane >> 4;            // half-warp -> head select
    const int sl = lane & 15;            // sub-lane: dims 4sl..4sl+3
    const int h = wid * 2 + hl;
    const int m0 = win * WIN;

    const __half* base = qkv + (size_t)m0 * N_QKV + h * 64 + sl * 4;

    float4 q[WIN], k[WIN], v[WIN];
#pragma unroll
    for (int i = 0; i < WIN; ++i) {
        const __half* r = base + (size_t)i * N_QKV;
        uint2 rq = *(const uint2*)(r);
        uint2 rk = *(const uint2*)(r + 512);
        uint2 rv = *(const uint2*)(r + 1024);
        float2 a, b;
        a = __half22float2(*(__half2*)&rq.x); b = __half22float2(*(__half2*)&rq.y);
        q[i] = make_float4(a.x, a.y, b.x, b.y);
        a = __half22float2(*(__half2*)&rk.x); b = __half22float2(*(__half2*)&rk.y);
        k[i] = make_float4(a.x, a.y, b.x, b.y);
        a = __half22float2(*(__half2*)&rv.x); b = __half22float2(*(__half2*)&rv.y);
        v[i] = make_float4(a.x, a.y, b.x, b.y);
    }

    float s[WIN][WIN];
#pragma unroll
    for (int i = 0; i < WIN; ++i)
#pragma unroll
        for (int j = 0; j < WIN; ++j) {
            float p = q[i].x * k[j].x + q[i].y * k[j].y +
                      q[i].z * k[j].z + q[i].w * k[j].w;
            p += __shfl_xor_sync(0xffffffffu, p, 8);
            p += __shfl_xor_sync(0xffffffffu, p, 4);
            p += __shfl_xor_sync(0xffffffffu, p, 2);
            p += __shfl_xor_sync(0xffffffffu, p, 1);
            s[i][j] = p * HSCALE;
        }

    // output dims d = 4sl..4sl+3 -> chunk 2h + (sl>=8), kin = (4sl)&31
    const int chunk = 2 * h + (sl >> 3);
    const int kin = (sl * 4) & 31;

#pragma unroll
    for (int i = 0; i < WIN; ++i) {
        float mx = s[i][0];
#pragma unroll
        for (int j = 1; j < WIN; ++j) mx = fmaxf(mx, s[i][j]);
        float sum = 0.0f;
#pragma unroll
        for (int j = 0; j < WIN; ++j) {
            s[i][j] = __expf(s[i][j] - mx);
            sum += s[i][j];
        }
        float inv = 1.0f / sum;
        float o0 = 0.f, o1 = 0.f, o2 = 0.f, o3 = 0.f;
#pragma unroll
        for (int j = 0; j < WIN; ++j) {
            float a = s[i][j] * inv;
            o0 += a * v[j].x;
            o1 += a * v[j].y;
            o2 += a * v[j].z;
            o3 += a * v[j].w;
        }
        int m = m0 + i;
        size_t tbase = ((size_t)(m >> 7) * NKC + chunk) * CH_A;
        __half2 p01 = __floats2half2_rn(o0, o1);
        __half2 p23 = __floats2half2_rn(o2, o3);
        *(uint32_t*)(oi + tbase + a_inner(m & 127, kin)) =
            *reinterpret_cast<uint32_t*>(&p01);
        *(uint32_t*)(oi + tbase + a_inner(m & 127, kin + 2)) =
            *reinterpret_cast<uint32_t*>(&p23);
    }
}

// ---------------------------------------------------------------------------
// kernel_launch: R15 structure (legal capture fork for conv_W overlap).
// ---------------------------------------------------------------------------
extern "C" void kernel_launch(void* const* d_in, const int* in_sizes, int n_in,
                              void* d_out, int out_size) {
    const float* x      = (const float*)d_in[0];
    const float* qkv_w  = (const float*)d_in[1];
    const float* qkv_b  = (const float*)d_in[2];
    const float* proj_w = (const float*)d_in[3];
    const float* proj_b = (const float*)d_in[4];
    float* out = (float*)d_out;

    __half* qkvp;
    char *Ai, *Oi, *B1, *B2;
    cudaGetSymbolAddress((void**)&qkvp, g_qkv);
    cudaGetSymbolAddress((void**)&Ai, gA_i);
    cudaGetSymbolAddress((void**)&Oi, gO_i);
    cudaGetSymbolAddress((void**)&B1, gB1_i);
    cudaGetSymbolAddress((void**)&B2, gB2_i);

    static bool init_done = false;
    static cudaStream_t s1;
    static cudaEvent_t evFork, evW;
    if (!init_done) {
        cudaFuncSetAttribute(gemm_hmma_1t<true>,
                             cudaFuncAttributeMaxDynamicSharedMemorySize,
                             NSTAGE * STAGE_B);
        cudaFuncSetAttribute(gemm_hmma_1t<false>,
                             cudaFuncAttributeMaxDynamicSharedMemorySize,
                             NSTAGE * STAGE_B);
        cudaStreamCreateWithFlags(&s1, cudaStreamNonBlocking);
        cudaEventCreateWithFlags(&evFork, cudaEventDisableTiming);
        cudaEventCreateWithFlags(&evW, cudaEventDisableTiming);
        init_done = true;
    }

    // legal fork: event on capture stream, side stream waits it first
    cudaEventRecord(evFork, 0);
    cudaStreamWaitEvent(s1, evFork, 0);

    conv_W_staged<<<(N_QKV / 128) * NKC, 256, 0, s1>>>(qkv_w, B1, N_QKV);
    conv_W_staged<<<(N_PROJ / 128) * NKC, 256, 0, s1>>>(proj_w, B2, N_PROJ);
    cudaEventRecord(evW, s1);

    conv_A_staged<<<(M_TOK / 128) * NKC, 256>>>(x, Ai);

    cudaStreamWaitEvent(0, evW, 0);

    {   // GEMM1 -> g_qkv (fp16)
        dim3 grid(N_QKV / 128, M_TOK / 128);
        gemm_hmma_1t<true><<<grid, 256, NSTAGE * STAGE_B>>>(Ai, B1, qkv_b,
                                                            qkvp, N_QKV);
    }

    win_attn_kernel<<<M_TOK / WIN, 128>>>(qkvp, Oi);

    {   // GEMM2 -> out (fp32)
        dim3 grid(N_PROJ / 128, M_TOK / 128);
        gemm_hmma_1t<false><<<grid, 256, NSTAGE * STAGE_B>>>(Oi, B2, proj_b,
                                                             out, N_PROJ);
    }
}

// round 17
// speedup vs baseline: 1.0895x; 1.0020x over previous
#include <cuda_runtime.h>
#include <cuda_fp16.h>
#include <cstdint>

// ---------------------------------------------------------------------------
// B=512,N=200,C=512,NH=8,WS=5,HD=64.  M=102400 tokens.
// R17: kernels EXACTLY as R16 (best 677.9us). New schedule: 2-way M-halves,
// attention halves on side stream overlap GEMM1-half-2 / GEMM2-half-1:
//   convs -> G1_0 -> { G1_1 || attn_0 } -> { G2_0 || attn_1 } -> G2_1
// ---------------------------------------------------------------------------
#define M_TOK   102400
#define K_DIM   512
#define N_QKV   1536
#define N_PROJ  512
#define WIN     5
#define HSCALE  0.125f
#define NKC     16        // K chunks of 32
#define CH_A    8192      // 128x32 fp16 A-image chunk bytes
#define CH_B    8192      // 32x128 fp16 B-image chunk bytes (paired frags)
#define STAGE_B 16384     // A(8K)+B(8K)
#define NSTAGE  3
#define MT_H    400       // m-tiles per half
#define TOK_H   51200     // tokens per half

// ---------------- scratch (device globals; no allocation) ------------------
__device__ __half  g_qkv[(size_t)M_TOK * N_QKV];
__device__ __half  gA_i[(size_t)M_TOK * K_DIM];
__device__ __half  gO_i[(size_t)M_TOK * K_DIM];
__device__ __half  gB1_i[(size_t)K_DIM * N_QKV];
__device__ __half  gB2_i[(size_t)K_DIM * N_PROJ];

// ---------------------------- helpers ---------------------------------------
__device__ __forceinline__ uint32_t smem_u32(const void* p) {
    uint32_t a;
    asm("{ .reg .u64 t; cvta.to.shared.u64 t, %1; cvt.u32.u64 %0, t; }"
        : "=r"(a) : "l"(p));
    return a;
}
__device__ __forceinline__ void cp16(uint32_t d, const void* s) {
    asm volatile("cp.async.cg.shared.global [%0], [%1], 16;"
                 :: "r"(d), "l"(s) : "memory");
}
__device__ __forceinline__ void cp_commit() {
    asm volatile("cp.async.commit_group;" ::: "memory");
}
__device__ __forceinline__ void cp_wait1() {
    asm volatile("cp.async.wait_group 1;" ::: "memory");
}
__device__ __forceinline__ void mma_f16(float4& d, uint4 a, uint32_t b0,
                                        uint32_t b1) {
    asm volatile(
        "mma.sync.aligned.m16n8k16.row.col.f32.f16.f16.f32 "
        "{%0,%1,%2,%3},{%4,%5,%6,%7},{%8,%9},{%0,%1,%2,%3};"
        : "+f"(d.x), "+f"(d.y), "+f"(d.z), "+f"(d.w)
        : "r"(a.x), "r"(a.y), "r"(a.z), "r"(a.w), "r"(b0), "r"(b1));
}
__device__ __forceinline__ unsigned short h_bits(__half h) {
    return *reinterpret_cast<unsigned short*>(&h);
}
__device__ __forceinline__ unsigned short h_single(float f) {
    __half hh = __float2half(f);
    return h_bits(hh);
}

// A-image inner offset (validated R3-R16):
__device__ __forceinline__ int a_inner(int row, int kin) {
    int kf = kin >> 4, mf = row >> 4, r = row & 15, c = kin & 15;
    return (kf * 8 + mf) * 512 + ((r & 7) * 4 + ((c & 7) >> 1)) * 16 +
           ((r >> 3) + ((c >> 3) << 1)) * 4 + (c & 1) * 2;
}
// Paired B-image inner offset (validated R6-R16):
__device__ __forceinline__ int bp_inner(int kr, int n) {
    int kf = kr >> 4, nfp = n >> 4, odd = (n >> 3) & 1;
    int t = (n & 7) * 4 + ((kr & 7) >> 1);
    return (kf * 8 + nfp) * 512 + t * 16 + odd * 8 + ((kr >> 3) & 1) * 4 +
           (kr & 1) * 2;
}

// ---------------------------------------------------------------------------
// conv A: x [M,512] fp32 -> single fp16 A images, smem-staged (R7/R12).
// ---------------------------------------------------------------------------
__global__ void __launch_bounds__(256)
conv_A_staged(const float* __restrict__ x, char* __restrict__ ai) {
    __shared__ char sh[CH_A];
    const int mt = blockIdx.x >> 4, kc = blockIdx.x & 15;
    const int t = threadIdx.x;
    const float* src = x + (size_t)mt * 128 * K_DIM + kc * 32;
#pragma unroll
    for (int i = 0; i < 4; ++i) {
        int f = t + i * 256;
        int row = f >> 3, c4 = (f & 7) * 4;
        float4 v = *(const float4*)(src + (size_t)row * K_DIM + c4);
        float vv[4] = {v.x, v.y, v.z, v.w};
#pragma unroll
        for (int jj = 0; jj < 4; ++jj)
            *(unsigned short*)(sh + a_inner(row, c4 + jj)) = h_single(vv[jj]);
    }
    __syncthreads();
    size_t ob = ((size_t)mt * NKC + kc) * CH_A;
    const uint4* shv = (const uint4*)sh;
    uint4* gh = (uint4*)(ai + ob);
    gh[t * 2] = shv[t * 2];
    gh[t * 2 + 1] = shv[t * 2 + 1];
}

// ---------------------------------------------------------------------------
// conv W: W [K,N] fp32 -> single fp16 paired B images, staged (R7/R12).
// ---------------------------------------------------------------------------
__global__ void __launch_bounds__(256)
conv_W_staged(const float* __restrict__ w, char* __restrict__ bi, int N) {
    __shared__ char sb[CH_B];
    const int nt = blockIdx.x >> 4, kc = blockIdx.x & 15;
    const int t = threadIdx.x;
    const float* src = w + (size_t)(kc * 32) * N + nt * 128;
#pragma unroll
    for (int i = 0; i < 4; ++i) {
        int f = t + i * 256;
        int kr = f >> 5, nc4 = (f & 31) * 4;
        float4 v = *(const float4*)(src + (size_t)kr * N + nc4);
        float vv[4] = {v.x, v.y, v.z, v.w};
#pragma unroll
        for (int jj = 0; jj < 4; ++jj)
            *(unsigned short*)(sb + bp_inner(kr, nc4 + jj)) = h_single(vv[jj]);
    }
    __syncthreads();
    size_t ob = ((size_t)nt * NKC + kc) * CH_B;
    const uint4* sv = (const uint4*)sb;
    uint4* gv = (uint4*)(bi + ob);
    gv[t * 2] = sv[t * 2];
    gv[t * 2 + 1] = sv[t * 2 + 1];
}

// ---------------------------------------------------------------------------
// 1-term fp16 HMMA GEMM (EXACT R7/R12 config — best measured).
// ---------------------------------------------------------------------------
template <bool HALF_OUT>
__global__ void __launch_bounds__(256, 2)
gemm_hmma_1t(const char* __restrict__ gAi, const char* __restrict__ gBi,
             const float* __restrict__ bias, void* __restrict__ Cv, int N) {
    extern __shared__ __align__(128) char smem[];
    const int tid = threadIdx.x;
    const int lane = tid & 31, wid = tid >> 5;
    const int wm = wid & 3, wn = wid >> 2;
    const uint32_t dynB = smem_u32(smem);

    const size_t aBase = (size_t)blockIdx.y * NKC * CH_A;
    const size_t bBase = (size_t)blockIdx.x * NKC * CH_B;

    float4 acc[2][8];
#pragma unroll
    for (int mi = 0; mi < 2; ++mi)
#pragma unroll
        for (int ni = 0; ni < 8; ++ni)
            acc[mi][ni] = make_float4(0.f, 0.f, 0.f, 0.f);

    auto issue = [&](int kc, int s) {
        uint32_t dst = dynB + s * STAGE_B;
        const char* ai = gAi + aBase + (size_t)kc * CH_A;
        const char* bi = gBi + bBase + (size_t)kc * CH_B;
        int off = tid * 16;
        cp16(dst + off, ai + off);
        cp16(dst + 4096 + off, ai + 4096 + off);
        cp16(dst + 8192 + off, bi + off);
        cp16(dst + 12288 + off, bi + 4096 + off);
    };

    issue(0, 0);
    cp_commit();
    issue(1, 1);
    cp_commit();

    for (int kc = 0; kc < NKC; ++kc) {
        const int s = kc % NSTAGE;
        cp_wait1();
        __syncthreads();
        if (kc + 2 < NKC) issue(kc + 2, (kc + 2) % NSTAGE);
        cp_commit();

        const char* st = smem + s * STAGE_B;
#pragma unroll
        for (int kf = 0; kf < 2; ++kf) {
            const char* af = st + (kf * 8 + wm * 2) * 512 + lane * 16;
            uint4 a0 = *(const uint4*)af;
            uint4 a1 = *(const uint4*)(af + 512);
            const char* bf =
                st + 8192 + (kf * 8 + wn * 4) * 512 + lane * 16;
#pragma unroll
            for (int p = 0; p < 4; ++p) {
                uint4 b = *(const uint4*)(bf + p * 512);
                int n0 = 2 * p, n1 = 2 * p + 1;
                mma_f16(acc[0][n0], a0, b.x, b.y);
                mma_f16(acc[1][n0], a1, b.x, b.y);
                mma_f16(acc[0][n1], a0, b.z, b.w);
                mma_f16(acc[1][n1], a1, b.z, b.w);
            }
        }
    }

    const int row0 = blockIdx.y * 128 + wm * 32 + (lane >> 2);
    const int col0 = blockIdx.x * 128 + wn * 64 + (lane & 3) * 2;
#pragma unroll
    for (int ni = 0; ni < 8; ++ni) {
        int c = col0 + ni * 8;
        float bx = bias[c], by = bias[c + 1];
#pragma unroll
        for (int mi = 0; mi < 2; ++mi) {
            float4 v = acc[mi][ni];
            if (HALF_OUT) {
                __half* C = (__half*)Cv;
                *(__half2*)(C + (size_t)(row0 + mi * 16) * N + c) =
                    __floats2half2_rn(v.x + bx, v.y + by);
                *(__half2*)(C + (size_t)(row0 + mi * 16 + 8) * N + c) =
                    __floats2half2_rn(v.z + bx, v.w + by);
            } else {
                float* C = (float*)Cv;
                *(float2*)(C + (size_t)(row0 + mi * 16) * N + c) =
                    make_float2(v.x + bx, v.y + by);
                *(float2*)(C + (size_t)(row0 + mi * 16 + 8) * N + c) =
                    make_float2(v.z + bx, v.w + by);
            }
        }
    }
}

// ---------------------------------------------------------------------------
// Windowed attention (EXACT R16): 16 lanes/head, warp = 2 heads, 4-stage
// butterfly, uint2 loads, packed 4B stores into A-images.
// ---------------------------------------------------------------------------
__global__ void __launch_bounds__(128)
win_attn_kernel(const __half* __restrict__ qkv, char* __restrict__ oi) {
    const int win = blockIdx.x;
    const int wid = threadIdx.x >> 5;
    const int lane = threadIdx.x & 31;
    const int hl = lane >> 4;
    const int sl = lane & 15;
    const int h = wid * 2 + hl;
    const int m0 = win * WIN;

    const __half* base = qkv + (size_t)m0 * N_QKV + h * 64 + sl * 4;

    float4 q[WIN], k[WIN], v[WIN];
#pragma unroll
    for (int i = 0; i < WIN; ++i) {
        const __half* r = base + (size_t)i * N_QKV;
        uint2 rq = *(const uint2*)(r);
        uint2 rk = *(const uint2*)(r + 512);
        uint2 rv = *(const uint2*)(r + 1024);
        float2 a, b;
        a = __half22float2(*(__half2*)&rq.x); b = __half22float2(*(__half2*)&rq.y);
        q[i] = make_float4(a.x, a.y, b.x, b.y);
        a = __half22float2(*(__half2*)&rk.x); b = __half22float2(*(__half2*)&rk.y);
        k[i] = make_float4(a.x, a.y, b.x, b.y);
        a = __half22float2(*(__half2*)&rv.x); b = __half22float2(*(__half2*)&rv.y);
        v[i] = make_float4(a.x, a.y, b.x, b.y);
    }

    float s[WIN][WIN];
#pragma unroll
    for (int i = 0; i < WIN; ++i)
#pragma unroll
        for (int j = 0; j < WIN; ++j) {
            float p = q[i].x * k[j].x + q[i].y * k[j].y +
                      q[i].z * k[j].z + q[i].w * k[j].w;
            p += __shfl_xor_sync(0xffffffffu, p, 8);
            p += __shfl_xor_sync(0xffffffffu, p, 4);
            p += __shfl_xor_sync(0xffffffffu, p, 2);
            p += __shfl_xor_sync(0xffffffffu, p, 1);
            s[i][j] = p * HSCALE;
        }

    const int chunk = 2 * h + (sl >> 3);
    const int kin = (sl * 4) & 31;

#pragma unroll
    for (int i = 0; i < WIN; ++i) {
        float mx = s[i][0];
#pragma unroll
        for (int j = 1; j < WIN; ++j) mx = fmaxf(mx, s[i][j]);
        float sum = 0.0f;
#pragma unroll
        for (int j = 0; j < WIN; ++j) {
            s[i][j] = __expf(s[i][j] - mx);
            sum += s[i][j];
        }
        float inv = 1.0f / sum;
        float o0 = 0.f, o1 = 0.f, o2 = 0.f, o3 = 0.f;
#pragma unroll
        for (int j = 0; j < WIN; ++j) {
            float a = s[i][j] * inv;
            o0 += a * v[j].x;
            o1 += a * v[j].y;
            o2 += a * v[j].z;
            o3 += a * v[j].w;
        }
        int m = m0 + i;
        size_t tbase = ((size_t)(m >> 7) * NKC + chunk) * CH_A;
        __half2 p01 = __floats2half2_rn(o0, o1);
        __half2 p23 = __floats2half2_rn(o2, o3);
        *(uint32_t*)(oi + tbase + a_inner(m & 127, kin)) =
            *reinterpret_cast<uint32_t*>(&p01);
        *(uint32_t*)(oi + tbase + a_inner(m & 127, kin + 2)) =
            *reinterpret_cast<uint32_t*>(&p23);
    }
}

// ---------------------------------------------------------------------------
// kernel_launch: 2-half pipeline with capture-legal fork (R15 pattern).
// main: convA, G1_0, G1_1, G2_0, G2_1
// s1  : convW x2, attn_0 (after G1_0), attn_1 (after G1_1)
// ---------------------------------------------------------------------------
extern "C" void kernel_launch(void* const* d_in, const int* in_sizes, int n_in,
                              void* d_out, int out_size) {
    const float* x      = (const float*)d_in[0];
    const float* qkv_w  = (const float*)d_in[1];
    const float* qkv_b  = (const float*)d_in[2];
    const float* proj_w = (const float*)d_in[3];
    const float* proj_b = (const float*)d_in[4];
    float* out = (float*)d_out;

    __half* qkvp;
    char *Ai, *Oi, *B1, *B2;
    cudaGetSymbolAddress((void**)&qkvp, g_qkv);
    cudaGetSymbolAddress((void**)&Ai, gA_i);
    cudaGetSymbolAddress((void**)&Oi, gO_i);
    cudaGetSymbolAddress((void**)&B1, gB1_i);
    cudaGetSymbolAddress((void**)&B2, gB2_i);

    static bool init_done = false;
    static cudaStream_t s1;
    static cudaEvent_t evFork, evW, evG1[2], evAt[2];
    if (!init_done) {
        cudaFuncSetAttribute(gemm_hmma_1t<true>,
                             cudaFuncAttributeMaxDynamicSharedMemorySize,
                             NSTAGE * STAGE_B);
        cudaFuncSetAttribute(gemm_hmma_1t<false>,
                             cudaFuncAttributeMaxDynamicSharedMemorySize,
                             NSTAGE * STAGE_B);
        cudaStreamCreateWithFlags(&s1, cudaStreamNonBlocking);
        cudaEventCreateWithFlags(&evFork, cudaEventDisableTiming);
        cudaEventCreateWithFlags(&evW, cudaEventDisableTiming);
        for (int i = 0; i < 2; ++i) {
            cudaEventCreateWithFlags(&evG1[i], cudaEventDisableTiming);
            cudaEventCreateWithFlags(&evAt[i], cudaEventDisableTiming);
        }
        init_done = true;
    }

    // capture-legal fork
    cudaEventRecord(evFork, 0);
    cudaStreamWaitEvent(s1, evFork, 0);

    // conv_W's on side stream; conv_A on main
    conv_W_staged<<<(N_QKV / 128) * NKC, 256, 0, s1>>>(qkv_w, B1, N_QKV);
    conv_W_staged<<<(N_PROJ / 128) * NKC, 256, 0, s1>>>(proj_w, B2, N_PROJ);
    cudaEventRecord(evW, s1);

    conv_A_staged<<<(M_TOK / 128) * NKC, 256>>>(x, Ai);
    cudaStreamWaitEvent(0, evW, 0);

    // GEMM1 halves on main stream
    for (int hf = 0; hf < 2; ++hf) {
        const char* Aq = Ai + (size_t)hf * MT_H * NKC * CH_A;
        __half* Cq = qkvp + (size_t)hf * TOK_H * N_QKV;
        dim3 grid(N_QKV / 128, MT_H);
        gemm_hmma_1t<true><<<grid, 256, NSTAGE * STAGE_B>>>(Aq, B1, qkv_b,
                                                            Cq, N_QKV);
        cudaEventRecord(evG1[hf], 0);
    }

    // attention halves on side stream (each gated on its GEMM1 half)
    for (int hf = 0; hf < 2; ++hf) {
        cudaStreamWaitEvent(s1, evG1[hf], 0);
        const __half* qkvq = qkvp + (size_t)hf * TOK_H * N_QKV;
        char* Oq = Oi + (size_t)hf * MT_H * NKC * CH_A;
        win_attn_kernel<<<TOK_H / WIN, 128, 0, s1>>>(qkvq, Oq);
        cudaEventRecord(evAt[hf], s1);
    }

    // GEMM2 halves on main stream (each gated on its attention half)
    for (int hf = 0; hf < 2; ++hf) {
        cudaStreamWaitEvent(0, evAt[hf], 0);
        const char* Oq = Oi + (size_t)hf * MT_H * NKC * CH_A;
        float* outq = out + (size_t)hf * TOK_H * N_PROJ;
        dim3 grid(N_PROJ / 128, MT_H);
        gemm_hmma_1t<false><<<grid, 256, NSTAGE * STAGE_B>>>(Oq, B2, proj_b,
                                                             outq, N_PROJ);
    }
}